// round 6
// baseline (speedup 1.0000x reference)
#include <cuda_runtime.h>
#include <math.h>

#define D_MODEL 1024
#define D_FF    2816
#define N_EXP   8
#define NSEG    9            // 8 routed experts + 1 shared (index 8)
#define T_TOKENS 4096
#define SEG     4096         // worst-case rows per segment

// ---------------- scratch (device globals; no allocations) ----------------
__device__ float g_xnorm[(size_t)T_TOKENS * D_MODEL];           // 16 MB
__device__ float g_H[(size_t)NSEG * SEG * D_FF];                // ~415 MB hidden acts
__device__ float g_Y[(size_t)NSEG * SEG * D_MODEL];             // ~151 MB expert outputs
__device__ int   g_idx[NSEG * SEG];                             // token id per (expert, slot)
__device__ float g_wt[N_EXP * SEG];                             // combine weight per slot
__device__ int   g_cnt[16];                                     // per-expert token counts
__device__ int   g_tokseg[T_TOKENS * 2];                        // token -> 2 segment-row ids

// ---------------------------------------------------------------------------
__global__ void zero_cnt_kernel() {
    if (threadIdx.x < 16) g_cnt[threadIdx.x] = 0;
}

// RMSNorm + gate logits + softmax top-2 + routing tables. One block per token.
__global__ __launch_bounds__(256) void route_kernel(const float* __restrict__ x,
                                                    const float* __restrict__ gw)
{
    const int t   = blockIdx.x;
    const int tid = threadIdx.x;
    __shared__ float s_x[D_MODEL];
    __shared__ float s_red[8];
    __shared__ float s_logit[N_EXP];
    __shared__ float s_rstd;

    const float* xr = x + (size_t)t * D_MODEL;
    float ss = 0.f;
    for (int i = tid; i < D_MODEL; i += 256) {
        float v = xr[i]; s_x[i] = v; ss += v * v;
    }
#pragma unroll
    for (int o = 16; o > 0; o >>= 1) ss += __shfl_xor_sync(0xffffffffu, ss, o);
    if ((tid & 31) == 0) s_red[tid >> 5] = ss;
    __syncthreads();
    if (tid == 0) {
        float tot = 0.f;
#pragma unroll
        for (int i = 0; i < 8; i++) tot += s_red[i];
        s_rstd = rsqrtf(tot * (1.0f / D_MODEL) + 1e-6f);
    }
    __syncthreads();
    const float rstd = s_rstd;
    for (int i = tid; i < D_MODEL; i += 256) {
        float v = s_x[i] * rstd;
        s_x[i] = v;
        g_xnorm[(size_t)t * D_MODEL + i] = v;
    }
    __syncthreads();

    // gate logits: warp w -> expert w
    const int w = tid >> 5, lane = tid & 31;
    const float* ge = gw + (size_t)w * D_MODEL;
    float acc = 0.f;
    for (int i = lane; i < D_MODEL; i += 32) acc += s_x[i] * ge[i];
#pragma unroll
    for (int o = 16; o > 0; o >>= 1) acc += __shfl_xor_sync(0xffffffffu, acc, o);
    if (lane == 0) s_logit[w] = acc;
    __syncthreads();

    if (tid == 0) {
        float l[8];
#pragma unroll
        for (int i = 0; i < 8; i++) l[i] = s_logit[i];
        int i0 = 0;
        for (int i = 1; i < 8; i++) if (l[i] > l[i0]) i0 = i;
        int i1 = (i0 == 0) ? 1 : 0;
        for (int i = 0; i < 8; i++) if (i != i0 && l[i] > l[i1]) i1 = i;
        // renormalized top-2 softmax weights (softmax denominator cancels)
        float e1 = expf(l[i1] - l[i0]);
        float w0 = 1.0f / (1.0f + e1);
        float w1v = 1.0f - w0;

        int s0 = atomicAdd(&g_cnt[i0], 1);
        g_idx[i0 * SEG + s0] = t;
        g_wt[i0 * SEG + s0]  = w0;
        g_tokseg[2 * t]      = i0 * SEG + s0;

        int s1 = atomicAdd(&g_cnt[i1], 1);
        g_idx[i1 * SEG + s1] = t;
        g_wt[i1 * SEG + s1]  = w1v;
        g_tokseg[2 * t + 1]  = i1 * SEG + s1;
    }
}

// ---------------------------------------------------------------------------
// Up GEMM (fused w1 & w3 + exact GELU): H[m,n] = gelu(A.W1^T) * (A.W3^T)
// Tile: 128(M) x 64(N) x 16(K), 256 threads, 8x4 per thread, dual accumulators.
__global__ __launch_bounds__(256) void up_gemm(
    const float* __restrict__ w1, const float* __restrict__ w3,
    const float* __restrict__ sw1, const float* __restrict__ sw3)
{
    const int e   = blockIdx.z;
    const int cnt = (e == N_EXP) ? T_TOKENS : g_cnt[e];
    const int m0  = blockIdx.y * 128;
    if (m0 >= cnt) return;
    const int n0  = blockIdx.x * 64;

    const float* B1 = (e == N_EXP) ? sw1 : (w1 + (size_t)e * D_FF * D_MODEL);
    const float* B3 = (e == N_EXP) ? sw3 : (w3 + (size_t)e * D_FF * D_MODEL);

    __shared__ float As[16][132];
    __shared__ float Bs1[16][68];
    __shared__ float Bs3[16][68];
    __shared__ int   s_row[128];

    const int tid = threadIdx.x;
    if (tid < 128) {
        int m = m0 + tid;
        int r = 0;
        if (m < cnt) r = (e == N_EXP) ? m : g_idx[e * SEG + m];
        s_row[tid] = r;
    }
    __syncthreads();

    const int arow = tid >> 1;
    const int ak   = (tid & 1) * 8;
    const int brow = tid >> 2;
    const int bk   = (tid & 3) * 4;

    const float* Ap  = g_xnorm + (size_t)s_row[arow] * D_MODEL;
    const float* B1p = B1 + (size_t)(n0 + brow) * D_MODEL;
    const float* B3p = B3 + (size_t)(n0 + brow) * D_MODEL;

    const int ty = tid >> 4, tx = tid & 15;
    const int mth = ty * 8, nth = tx * 4;

    float acc1[8][4] = {};
    float acc2[8][4] = {};

    for (int k0 = 0; k0 < D_MODEL; k0 += 16) {
        float4 a0 = *(const float4*)(Ap  + k0 + ak);
        float4 a1 = *(const float4*)(Ap  + k0 + ak + 4);
        float4 b1 = *(const float4*)(B1p + k0 + bk);
        float4 b3 = *(const float4*)(B3p + k0 + bk);
        __syncthreads();
        As[ak+0][arow]=a0.x; As[ak+1][arow]=a0.y; As[ak+2][arow]=a0.z; As[ak+3][arow]=a0.w;
        As[ak+4][arow]=a1.x; As[ak+5][arow]=a1.y; As[ak+6][arow]=a1.z; As[ak+7][arow]=a1.w;
        Bs1[bk+0][brow]=b1.x; Bs1[bk+1][brow]=b1.y; Bs1[bk+2][brow]=b1.z; Bs1[bk+3][brow]=b1.w;
        Bs3[bk+0][brow]=b3.x; Bs3[bk+1][brow]=b3.y; Bs3[bk+2][brow]=b3.z; Bs3[bk+3][brow]=b3.w;
        __syncthreads();
#pragma unroll
        for (int kk = 0; kk < 16; kk++) {
            float4 av0 = *(const float4*)&As[kk][mth];
            float4 av1 = *(const float4*)&As[kk][mth + 4];
            float4 bv1 = *(const float4*)&Bs1[kk][nth];
            float4 bv3 = *(const float4*)&Bs3[kk][nth];
            float a[8]  = {av0.x,av0.y,av0.z,av0.w,av1.x,av1.y,av1.z,av1.w};
            float p1[4] = {bv1.x,bv1.y,bv1.z,bv1.w};
            float p3[4] = {bv3.x,bv3.y,bv3.z,bv3.w};
#pragma unroll
            for (int i = 0; i < 8; i++)
#pragma unroll
                for (int j = 0; j < 4; j++) {
                    acc1[i][j] += a[i] * p1[j];
                    acc2[i][j] += a[i] * p3[j];
                }
        }
    }

#pragma unroll
    for (int i = 0; i < 8; i++) {
        int m = m0 + mth + i;
        if (m >= cnt) continue;
        float* Hp = g_H + ((size_t)e * SEG + m) * D_FF + n0 + nth;
#pragma unroll
        for (int j = 0; j < 4; j++) {
            float u = acc1[i][j];
            Hp[j] = u * normcdff(u) * acc2[i][j];   // exact GELU * gate
        }
    }
}

// ---------------------------------------------------------------------------
// Down GEMM: Y[m,n] = (H . W2^T) * combine_weight
__global__ __launch_bounds__(256) void down_gemm(
    const float* __restrict__ w2, const float* __restrict__ sw2)
{
    const int e   = blockIdx.z;
    const int cnt = (e == N_EXP) ? T_TOKENS : g_cnt[e];
    const int m0  = blockIdx.y * 128;
    if (m0 >= cnt) return;
    const int n0  = blockIdx.x * 64;
    const float* B = (e == N_EXP) ? sw2 : (w2 + (size_t)e * D_MODEL * D_FF);

    __shared__ float As[16][132];
    __shared__ float Bs[16][68];

    const int tid  = threadIdx.x;
    const int arow = tid >> 1;
    const int ak   = (tid & 1) * 8;
    const int brow = tid >> 2;
    const int bk   = (tid & 3) * 4;

    const float* Ap = g_H + ((size_t)e * SEG + (m0 + arow)) * D_FF;  // in-bounds even past cnt
    const float* Bp = B + (size_t)(n0 + brow) * D_FF;

    const int ty = tid >> 4, tx = tid & 15;
    const int mth = ty * 8, nth = tx * 4;
    float acc[8][4] = {};

    for (int k0 = 0; k0 < D_FF; k0 += 16) {
        float4 a0 = *(const float4*)(Ap + k0 + ak);
        float4 a1 = *(const float4*)(Ap + k0 + ak + 4);
        float4 b0 = *(const float4*)(Bp + k0 + bk);
        __syncthreads();
        As[ak+0][arow]=a0.x; As[ak+1][arow]=a0.y; As[ak+2][arow]=a0.z; As[ak+3][arow]=a0.w;
        As[ak+4][arow]=a1.x; As[ak+5][arow]=a1.y; As[ak+6][arow]=a1.z; As[ak+7][arow]=a1.w;
        Bs[bk+0][brow]=b0.x; Bs[bk+1][brow]=b0.y; Bs[bk+2][brow]=b0.z; Bs[bk+3][brow]=b0.w;
        __syncthreads();
#pragma unroll
        for (int kk = 0; kk < 16; kk++) {
            float4 av0 = *(const float4*)&As[kk][mth];
            float4 av1 = *(const float4*)&As[kk][mth + 4];
            float4 bv  = *(const float4*)&Bs[kk][nth];
            float a[8] = {av0.x,av0.y,av0.z,av0.w,av1.x,av1.y,av1.z,av1.w};
            float b[4] = {bv.x,bv.y,bv.z,bv.w};
#pragma unroll
            for (int i = 0; i < 8; i++)
#pragma unroll
                for (int j = 0; j < 4; j++)
                    acc[i][j] += a[i] * b[j];
        }
    }

#pragma unroll
    for (int i = 0; i < 8; i++) {
        int m = m0 + mth + i;
        if (m >= cnt) continue;
        float wt = (e == N_EXP) ? 1.0f : g_wt[e * SEG + m];
        float* Yp = g_Y + ((size_t)e * SEG + m) * D_MODEL + n0 + nth;
#pragma unroll
        for (int j = 0; j < 4; j++) Yp[j] = acc[i][j] * wt;
    }
}

// ---------------------------------------------------------------------------
// out = identity + shared_expert + routed slot0 + routed slot1 (deterministic)
__global__ void combine_kernel(const float* __restrict__ x, float* __restrict__ out)
{
    const int t = blockIdx.x;
    const int s0 = g_tokseg[2 * t], s1 = g_tokseg[2 * t + 1];
    const float* xr  = x + (size_t)t * D_MODEL;
    const float* ysh = g_Y + ((size_t)N_EXP * SEG + t) * D_MODEL;
    const float* y0  = g_Y + (size_t)s0 * D_MODEL;
    const float* y1  = g_Y + (size_t)s1 * D_MODEL;
    float* o = out + (size_t)t * D_MODEL;
    for (int i = threadIdx.x; i < D_MODEL; i += blockDim.x)
        o[i] = xr[i] + ysh[i] + y0[i] + y1[i];
}

// ---------------------------------------------------------------------------
extern "C" void kernel_launch(void* const* d_in, const int* in_sizes, int n_in,
                              void* d_out, int out_size)
{
    const float* x   = (const float*)d_in[0];
    const float* gw  = (const float*)d_in[1];
    const float* w1  = (const float*)d_in[2];
    const float* w2  = (const float*)d_in[3];
    const float* w3  = (const float*)d_in[4];
    const float* sw1 = (const float*)d_in[5];
    const float* sw2 = (const float*)d_in[6];
    const float* sw3 = (const float*)d_in[7];
    float* out = (float*)d_out;

    zero_cnt_kernel<<<1, 32>>>();
    route_kernel<<<T_TOKENS, 256>>>(x, gw);
    up_gemm<<<dim3(D_FF / 64, T_TOKENS / 128, NSEG), 256>>>(w1, w3, sw1, sw3);
    down_gemm<<<dim3(D_MODEL / 64, T_TOKENS / 128, NSEG), 256>>>(w2, sw2);
    combine_kernel<<<T_TOKENS, 256>>>(x, out);
}

// round 10
// speedup vs baseline: 3.0172x; 3.0172x over previous
#include <cuda_runtime.h>
#include <math.h>
#include <stdint.h>

#define D_MODEL 1024
#define D_FF    2816
#define N_EXP   8
#define NSEG    9            // 8 routed experts + 1 shared (index 8)
#define T_TOKENS 4096
#define SEG     4096

// ---------------- scratch (device globals; no allocations) ----------------
__device__ float g_xnorm[(size_t)T_TOKENS * D_MODEL];   // tf32-rounded activations
__device__ float g_H[(size_t)NSEG * SEG * D_FF];        // tf32-rounded hidden acts
__device__ float g_Y[(size_t)NSEG * SEG * D_MODEL];     // expert outputs (fp32)
__device__ int   g_idx[NSEG * SEG];
__device__ float g_wt[N_EXP * SEG];
__device__ int   g_cnt[16];
__device__ int   g_tokseg[T_TOKENS * 2];

// ---------------- helpers ----------------
__device__ __forceinline__ uint32_t smem_u32(const void* p) {
    uint32_t a;
    asm("{ .reg .u64 t; cvta.to.shared.u64 t, %1; cvt.u32.u64 %0, t; }" : "=r"(a) : "l"(p));
    return a;
}
__device__ __forceinline__ float tf32r(float x) {        // round-to-nearest tf32
    uint32_t u = __float_as_uint(x), v;
    asm("cvt.rna.tf32.f32 %0, %1;" : "=r"(v) : "r"(u));
    return __uint_as_float(v);
}
__device__ __forceinline__ void mma8(float c[4], const uint32_t a[4], const uint32_t b[2]) {
    asm volatile(
        "mma.sync.aligned.m16n8k8.row.col.f32.tf32.tf32.f32 "
        "{%0,%1,%2,%3}, {%4,%5,%6,%7}, {%8,%9}, {%0,%1,%2,%3};"
        : "+f"(c[0]), "+f"(c[1]), "+f"(c[2]), "+f"(c[3])
        : "r"(a[0]), "r"(a[1]), "r"(a[2]), "r"(a[3]), "r"(b[0]), "r"(b[1]));
}
#define CP_ASYNC16(d, s) asm volatile("cp.async.cg.shared.global [%0], [%1], 16;" :: "r"(d), "l"(s) : "memory")
#define CP_COMMIT()      asm volatile("cp.async.commit_group;" ::: "memory")
#define CP_WAIT0()       asm volatile("cp.async.wait_group 0;" ::: "memory")

// smem stage layouts (floats), padded stride 36 -> conflict-free fragment LDS
#define A_ELEMS   (128 * 36)              // 4608
#define B_ELEMS   (64 * 36)               // 2304
#define UP_STAGE  (A_ELEMS + 2 * B_ELEMS) // 9216 floats
#define DN_STAGE  (A_ELEMS + B_ELEMS)     // 6912 floats
#define UP_SMEM   (2 * UP_STAGE * 4)      // 73728 B
#define DN_SMEM   (2 * DN_STAGE * 4)      // 55296 B

// ---------------------------------------------------------------------------
__global__ void zero_cnt_kernel() {
    if (threadIdx.x < 16) g_cnt[threadIdx.x] = 0;
}

// RMSNorm + gate + top-2 routing. One block per token.
__global__ __launch_bounds__(256) void route_kernel(const float* __restrict__ x,
                                                    const float* __restrict__ gw)
{
    const int t   = blockIdx.x;
    const int tid = threadIdx.x;
    __shared__ float s_x[D_MODEL];
    __shared__ float s_red[8];
    __shared__ float s_logit[N_EXP];
    __shared__ float s_rstd;

    const float* xr = x + (size_t)t * D_MODEL;
    float ss = 0.f;
    for (int i = tid; i < D_MODEL; i += 256) {
        float v = xr[i]; s_x[i] = v; ss += v * v;
    }
#pragma unroll
    for (int o = 16; o > 0; o >>= 1) ss += __shfl_xor_sync(0xffffffffu, ss, o);
    if ((tid & 31) == 0) s_red[tid >> 5] = ss;
    __syncthreads();
    if (tid == 0) {
        float tot = 0.f;
#pragma unroll
        for (int i = 0; i < 8; i++) tot += s_red[i];
        s_rstd = rsqrtf(tot * (1.0f / D_MODEL) + 1e-6f);
    }
    __syncthreads();
    const float rstd = s_rstd;
    for (int i = tid; i < D_MODEL; i += 256) {
        float v = s_x[i] * rstd;
        s_x[i] = v;
        g_xnorm[(size_t)t * D_MODEL + i] = tf32r(v);   // pre-rounded for tf32 MMA
    }
    __syncthreads();

    const int w = tid >> 5, lane = tid & 31;
    const float* ge = gw + (size_t)w * D_MODEL;
    float acc = 0.f;
    for (int i = lane; i < D_MODEL; i += 32) acc += s_x[i] * ge[i];
#pragma unroll
    for (int o = 16; o > 0; o >>= 1) acc += __shfl_xor_sync(0xffffffffu, acc, o);
    if (lane == 0) s_logit[w] = acc;
    __syncthreads();

    if (tid == 0) {
        float l[8];
#pragma unroll
        for (int i = 0; i < 8; i++) l[i] = s_logit[i];
        int i0 = 0;
        for (int i = 1; i < 8; i++) if (l[i] > l[i0]) i0 = i;
        int i1 = (i0 == 0) ? 1 : 0;
        for (int i = 0; i < 8; i++) if (i != i0 && l[i] > l[i1]) i1 = i;
        float e1 = expf(l[i1] - l[i0]);
        float w0 = 1.0f / (1.0f + e1);
        float w1v = 1.0f - w0;

        int s0 = atomicAdd(&g_cnt[i0], 1);
        g_idx[i0 * SEG + s0] = t;
        g_wt[i0 * SEG + s0]  = w0;
        g_tokseg[2 * t]      = i0 * SEG + s0;

        int s1 = atomicAdd(&g_cnt[i1], 1);
        g_idx[i1 * SEG + s1] = t;
        g_wt[i1 * SEG + s1]  = w1v;
        g_tokseg[2 * t + 1]  = i1 * SEG + s1;
    }
}

// ---------------------------------------------------------------------------
// Up GEMM (tf32 mma.sync): CTA tile 128(M) x 64(N), dual B (w1 & w3), K-chunk 32.
// 8 warps 4x2; warp tile 32x32; m16n8k8 fragments.
__global__ __launch_bounds__(256)
void up_mma(const float* __restrict__ w1, const float* __restrict__ w3,
            const float* __restrict__ sw1, const float* __restrict__ sw3)
{
    const int e   = blockIdx.z;
    const int cnt = (e == N_EXP) ? T_TOKENS : g_cnt[e];
    const int m0  = blockIdx.y * 128;
    if (m0 >= cnt) return;
    const int n0  = blockIdx.x * 64;
    const float* B1 = (e == N_EXP) ? sw1 : (w1 + (size_t)e * D_FF * D_MODEL);
    const float* B3 = (e == N_EXP) ? sw3 : (w3 + (size_t)e * D_FF * D_MODEL);

    extern __shared__ float dynf[];
    const uint32_t sbase = smem_u32(dynf);

    __shared__ int s_row[128];
    const int tid  = threadIdx.x;
    const int wid  = tid >> 5;
    const int lane = tid & 31;
    const int g    = lane >> 2;
    const int p    = lane & 3;
    const int wm   = wid >> 1;     // 0..3
    const int wn   = wid & 1;      // 0..1

    if (tid < 128) {
        int m = m0 + tid;
        s_row[tid] = (m < cnt) ? ((e == N_EXP) ? m : g_idx[e * SEG + m]) : 0;
    }
    __syncthreads();

    float acc1[2][4][4] = {};
    float acc2[2][4][4] = {};

    auto cpA = [&](int k0, int s) {
        const uint32_t As = sbase + s * (UP_STAGE * 4);
#pragma unroll
        for (int it = 0; it < 4; it++) {
            int id = it * 256 + tid;
            int r = id >> 3, c = id & 7;
            const float* src = g_xnorm + (size_t)s_row[r] * D_MODEL + k0 + c * 4;
            CP_ASYNC16(As + r * 144 + c * 16, src);
        }
        CP_COMMIT();
    };
    auto ldgB = [&](int k0, float4 br[4]) {
#pragma unroll
        for (int it = 0; it < 2; it++) {
            int id = it * 256 + tid;
            int r = id >> 3, c = id & 7;
            br[it]     = *(const float4*)(B1 + (size_t)(n0 + r) * D_MODEL + k0 + c * 4);
            br[2 + it] = *(const float4*)(B3 + (size_t)(n0 + r) * D_MODEL + k0 + c * 4);
        }
    };
    auto stsB = [&](int s, const float4 br[4]) {
        float* b1s = dynf + s * UP_STAGE + A_ELEMS;
        float* b3s = b1s + B_ELEMS;
#pragma unroll
        for (int it = 0; it < 2; it++) {
            int id = it * 256 + tid;
            int r = id >> 3, c = id & 7;
            float4 v = br[it];
            float4 o = {tf32r(v.x), tf32r(v.y), tf32r(v.z), tf32r(v.w)};
            *(float4*)(b1s + r * 36 + c * 4) = o;
            v = br[2 + it];
            float4 o3 = {tf32r(v.x), tf32r(v.y), tf32r(v.z), tf32r(v.w)};
            *(float4*)(b3s + r * 36 + c * 4) = o3;
        }
    };
    auto compute = [&](int s) {
        const float* As  = dynf + s * UP_STAGE + (wm * 32) * 36;
        const float* B1s = dynf + s * UP_STAGE + A_ELEMS + (wn * 32) * 36;
        const float* B3s = B1s + B_ELEMS;
#pragma unroll
        for (int kk = 0; kk < 32; kk += 8) {
            uint32_t a[2][4];
#pragma unroll
            for (int mi = 0; mi < 2; mi++) {
                const float* ap = As + (mi * 16 + g) * 36 + kk + p;
                a[mi][0] = __float_as_uint(ap[0]);
                a[mi][2] = __float_as_uint(ap[4]);
                a[mi][1] = __float_as_uint(ap[8 * 36]);
                a[mi][3] = __float_as_uint(ap[8 * 36 + 4]);
            }
#pragma unroll
            for (int ni = 0; ni < 4; ni++) {
                const float* bp1 = B1s + (ni * 8 + g) * 36 + kk + p;
                const float* bp3 = B3s + (ni * 8 + g) * 36 + kk + p;
                uint32_t b1[2] = {__float_as_uint(bp1[0]), __float_as_uint(bp1[4])};
                uint32_t b3[2] = {__float_as_uint(bp3[0]), __float_as_uint(bp3[4])};
#pragma unroll
                for (int mi = 0; mi < 2; mi++) {
                    mma8(acc1[mi][ni], a[mi], b1);
                    mma8(acc2[mi][ni], a[mi], b3);
                }
            }
        }
    };

    const int NK = D_MODEL / 32;   // 32
    {
        float4 br[4];
        cpA(0, 0);
        ldgB(0, br);
        stsB(0, br);
        CP_WAIT0();
        __syncthreads();
    }
    for (int k = 0; k < NK; k++) {
        const int cur = k & 1;
        float4 br[4];
        const bool more = (k + 1 < NK);
        if (more) { ldgB((k + 1) * 32, br); cpA((k + 1) * 32, cur ^ 1); }
        compute(cur);
        if (more) { stsB(cur ^ 1, br); CP_WAIT0(); }
        __syncthreads();
    }

    // Epilogue: gelu(u)*v -> g_H (tf32-rounded)
#pragma unroll
    for (int mi = 0; mi < 2; mi++) {
#pragma unroll
        for (int half = 0; half < 2; half++) {
            int m = m0 + wm * 32 + mi * 16 + g + half * 8;
            if (m >= cnt) continue;
            float* Hp = g_H + ((size_t)e * SEG + m) * D_FF + n0 + wn * 32;
#pragma unroll
            for (int ni = 0; ni < 4; ni++) {
                float u0 = acc1[mi][ni][half * 2 + 0];
                float u1 = acc1[mi][ni][half * 2 + 1];
                float v0 = acc2[mi][ni][half * 2 + 0];
                float v1 = acc2[mi][ni][half * 2 + 1];
                float2 o = {tf32r(u0 * normcdff(u0) * v0),
                            tf32r(u1 * normcdff(u1) * v1)};
                *(float2*)(Hp + ni * 8 + 2 * p) = o;
            }
        }
    }
}

// ---------------------------------------------------------------------------
// Down GEMM (tf32 mma.sync): CTA tile 128(M) x 64(N), K-chunk 32 over D_FF.
__global__ __launch_bounds__(256)
void down_mma(const float* __restrict__ w2, const float* __restrict__ sw2)
{
    const int e   = blockIdx.z;
    const int cnt = (e == N_EXP) ? T_TOKENS : g_cnt[e];
    const int m0  = blockIdx.y * 128;
    if (m0 >= cnt) return;
    const int n0  = blockIdx.x * 64;
    const float* B = (e == N_EXP) ? sw2 : (w2 + (size_t)e * D_MODEL * D_FF);

    extern __shared__ float dynf[];
    const uint32_t sbase = smem_u32(dynf);

    const int tid  = threadIdx.x;
    const int wid  = tid >> 5;
    const int lane = tid & 31;
    const int g    = lane >> 2;
    const int p    = lane & 3;
    const int wm   = wid >> 1;
    const int wn   = wid & 1;

    const float* Abase = g_H + ((size_t)e * SEG + m0) * D_FF;
    float acc[2][4][4] = {};

    auto cpA = [&](int k0, int s) {
        const uint32_t As = sbase + s * (DN_STAGE * 4);
#pragma unroll
        for (int it = 0; it < 4; it++) {
            int id = it * 256 + tid;
            int r = id >> 3, c = id & 7;
            const float* src = Abase + (size_t)r * D_FF + k0 + c * 4;
            CP_ASYNC16(As + r * 144 + c * 16, src);
        }
        CP_COMMIT();
    };
    auto ldgB = [&](int k0, float4 br[2]) {
#pragma unroll
        for (int it = 0; it < 2; it++) {
            int id = it * 256 + tid;
            int r = id >> 3, c = id & 7;
            br[it] = *(const float4*)(B + (size_t)(n0 + r) * D_FF + k0 + c * 4);
        }
    };
    auto stsB = [&](int s, const float4 br[2]) {
        float* bs = dynf + s * DN_STAGE + A_ELEMS;
#pragma unroll
        for (int it = 0; it < 2; it++) {
            int id = it * 256 + tid;
            int r = id >> 3, c = id & 7;
            float4 v = br[it];
            float4 o = {tf32r(v.x), tf32r(v.y), tf32r(v.z), tf32r(v.w)};
            *(float4*)(bs + r * 36 + c * 4) = o;
        }
    };
    auto compute = [&](int s) {
        const float* As = dynf + s * DN_STAGE + (wm * 32) * 36;
        const float* Bs = dynf + s * DN_STAGE + A_ELEMS + (wn * 32) * 36;
#pragma unroll
        for (int kk = 0; kk < 32; kk += 8) {
            uint32_t a[2][4];
#pragma unroll
            for (int mi = 0; mi < 2; mi++) {
                const float* ap = As + (mi * 16 + g) * 36 + kk + p;
                a[mi][0] = __float_as_uint(ap[0]);
                a[mi][2] = __float_as_uint(ap[4]);
                a[mi][1] = __float_as_uint(ap[8 * 36]);
                a[mi][3] = __float_as_uint(ap[8 * 36 + 4]);
            }
#pragma unroll
            for (int ni = 0; ni < 4; ni++) {
                const float* bp = Bs + (ni * 8 + g) * 36 + kk + p;
                uint32_t b[2] = {__float_as_uint(bp[0]), __float_as_uint(bp[4])};
#pragma unroll
                for (int mi = 0; mi < 2; mi++)
                    mma8(acc[mi][ni], a[mi], b);
            }
        }
    };

    const int NK = D_FF / 32;   // 88
    {
        float4 br[2];
        cpA(0, 0);
        ldgB(0, br);
        stsB(0, br);
        CP_WAIT0();
        __syncthreads();
    }
    for (int k = 0; k < NK; k++) {
        const int cur = k & 1;
        float4 br[2];
        const bool more = (k + 1 < NK);
        if (more) { ldgB((k + 1) * 32, br); cpA((k + 1) * 32, cur ^ 1); }
        compute(cur);
        if (more) { stsB(cur ^ 1, br); CP_WAIT0(); }
        __syncthreads();
    }

    // Epilogue: scale by combine weight -> g_Y
#pragma unroll
    for (int mi = 0; mi < 2; mi++) {
#pragma unroll
        for (int half = 0; half < 2; half++) {
            int m = m0 + wm * 32 + mi * 16 + g + half * 8;
            if (m >= cnt) continue;
            float wt = (e == N_EXP) ? 1.0f : g_wt[e * SEG + m];
            float* Yp = g_Y + ((size_t)e * SEG + m) * D_MODEL + n0 + wn * 32;
#pragma unroll
            for (int ni = 0; ni < 4; ni++) {
                float2 o = {acc[mi][ni][half * 2 + 0] * wt,
                            acc[mi][ni][half * 2 + 1] * wt};
                *(float2*)(Yp + ni * 8 + 2 * p) = o;
            }
        }
    }
}

// ---------------------------------------------------------------------------
__global__ void combine_kernel(const float* __restrict__ x, float* __restrict__ out)
{
    const int t = blockIdx.x;
    const int s0 = g_tokseg[2 * t], s1 = g_tokseg[2 * t + 1];
    const float* xr  = x + (size_t)t * D_MODEL;
    const float* ysh = g_Y + ((size_t)N_EXP * SEG + t) * D_MODEL;
    const float* y0  = g_Y + (size_t)s0 * D_MODEL;
    const float* y1  = g_Y + (size_t)s1 * D_MODEL;
    float* o = out + (size_t)t * D_MODEL;
    for (int i = threadIdx.x; i < D_MODEL; i += blockDim.x)
        o[i] = xr[i] + ysh[i] + y0[i] + y1[i];
}

// ---------------------------------------------------------------------------
extern "C" void kernel_launch(void* const* d_in, const int* in_sizes, int n_in,
                              void* d_out, int out_size)
{
    const float* x   = (const float*)d_in[0];
    const float* gw  = (const float*)d_in[1];
    const float* w1  = (const float*)d_in[2];
    const float* w2  = (const float*)d_in[3];
    const float* w3  = (const float*)d_in[4];
    const float* sw1 = (const float*)d_in[5];
    const float* sw2 = (const float*)d_in[6];
    const float* sw3 = (const float*)d_in[7];
    float* out = (float*)d_out;

    cudaFuncSetAttribute(up_mma,   cudaFuncAttributeMaxDynamicSharedMemorySize, UP_SMEM);
    cudaFuncSetAttribute(down_mma, cudaFuncAttributeMaxDynamicSharedMemorySize, DN_SMEM);

    zero_cnt_kernel<<<1, 32>>>();
    route_kernel<<<T_TOKENS, 256>>>(x, gw);
    up_mma<<<dim3(D_FF / 64, T_TOKENS / 128, NSEG), 256, UP_SMEM>>>(w1, w3, sw1, sw3);
    down_mma<<<dim3(D_MODEL / 64, T_TOKENS / 128, NSEG), 256, DN_SMEM>>>(w2, sw2);
    combine_kernel<<<T_TOKENS, 256>>>(x, out);
}

// round 12
// speedup vs baseline: 4.9158x; 1.6293x over previous
#include <cuda_runtime.h>
#include <cuda_fp16.h>
#include <math.h>
#include <stdint.h>

#define D_MODEL 1024
#define D_FF    2816
#define N_EXP   8
#define NSEG    9            // 8 routed experts + 1 shared (index 8)
#define T_TOKENS 4096
#define SEG     4096

// ---------------- scratch (device globals; no allocations) ----------------
__device__ __half g_xnh[(size_t)T_TOKENS * D_MODEL];            // fp16 normed acts
__device__ __half g_w13r[(size_t)NSEG * 2 * D_FF * D_MODEL];    // interleaved w1/w3 fp16
__device__ __half g_w2r[(size_t)NSEG * D_MODEL * D_FF];         // w2 fp16
__device__ __half g_H[(size_t)NSEG * SEG * D_FF];               // hidden acts fp16
__device__ float  g_Y[(size_t)NSEG * SEG * D_MODEL];            // expert outputs fp32
__device__ int    g_idx[NSEG * SEG];
__device__ float  g_wt[N_EXP * SEG];
__device__ int    g_cnt[16];
__device__ int    g_tokseg[T_TOKENS * 2];

// ---------------- helpers ----------------
__device__ __forceinline__ uint32_t smem_u32(const void* p) {
    uint32_t a;
    asm("{ .reg .u64 t; cvta.to.shared.u64 t, %1; cvt.u32.u64 %0, t; }" : "=r"(a) : "l"(p));
    return a;
}
__device__ __forceinline__ void mma16(float c[4], const uint32_t a[4],
                                      uint32_t b0, uint32_t b1) {
    asm volatile(
        "mma.sync.aligned.m16n8k16.row.col.f32.f16.f16.f32 "
        "{%0,%1,%2,%3}, {%4,%5,%6,%7}, {%8,%9}, {%0,%1,%2,%3};"
        : "+f"(c[0]), "+f"(c[1]), "+f"(c[2]), "+f"(c[3])
        : "r"(a[0]), "r"(a[1]), "r"(a[2]), "r"(a[3]), "r"(b0), "r"(b1));
}
#define CP_ASYNC16(d, s) asm volatile("cp.async.cg.shared.global [%0], [%1], 16;" :: "r"(d), "l"(s) : "memory")
#define CP_COMMIT()      asm volatile("cp.async.commit_group;" ::: "memory")
#define CP_WAIT2()       asm volatile("cp.async.wait_group 2;" ::: "memory")

// stage: A-rows + B-rows, stride 40 halves (80B: conflict-free scalar LDS & cp.async)
#define STRIDE     40
#define STAGE_H    ((128 + 256) * STRIDE)     // 15360 halves = 30720 B
#define N_STAGES   4
#define SMEM_DYN   (N_STAGES * STAGE_H * 2)   // 122880 B

// ---------------------------------------------------------------------------
__global__ void zero_cnt_kernel() {
    if (threadIdx.x < 16) g_cnt[threadIdx.x] = 0;
}

// weights -> fp16, w1/w3 interleaved by output column: row 2j=w1[j], 2j+1=w3[j]
__global__ __launch_bounds__(256) void conv_w13(
    const float* __restrict__ w1, const float* __restrict__ w3,
    const float* __restrict__ sw1, const float* __restrict__ sw3)
{
    const int r = blockIdx.x;               // 0 .. 9*5632-1
    const int e = r / (2 * D_FF);
    const int rr = r % (2 * D_FF);
    const int j = rr >> 1, h = rr & 1;
    const float* src;
    if (e < N_EXP) src = (h ? w3 : w1) + ((size_t)e * D_FF + j) * D_MODEL;
    else           src = (h ? sw3 : sw1) + (size_t)j * D_MODEL;
    __half* dst = g_w13r + (size_t)r * D_MODEL;
    const float4* s4 = (const float4*)src;
    int i = threadIdx.x;
    float4 v = s4[i];
    __half2 h0 = __floats2half2_rn(v.x, v.y);
    __half2 h1 = __floats2half2_rn(v.z, v.w);
    *(__half2*)(dst + i * 4)     = h0;
    *(__half2*)(dst + i * 4 + 2) = h1;
}

__global__ __launch_bounds__(256) void conv_w2(
    const float* __restrict__ w2, const float* __restrict__ sw2)
{
    const int r = blockIdx.x;               // 0 .. 9*1024-1
    const int e = r / D_MODEL, rr = r % D_MODEL;
    const float* src = (e < N_EXP) ? (w2 + ((size_t)e * D_MODEL + rr) * D_FF)
                                   : (sw2 + (size_t)rr * D_FF);
    __half* dst = g_w2r + (size_t)r * D_FF;
    const float4* s4 = (const float4*)src;
    for (int i = threadIdx.x; i < D_FF / 4; i += 256) {
        float4 v = s4[i];
        __half2 h0 = __floats2half2_rn(v.x, v.y);
        __half2 h1 = __floats2half2_rn(v.z, v.w);
        *(__half2*)(dst + i * 4)     = h0;
        *(__half2*)(dst + i * 4 + 2) = h1;
    }
}

// RMSNorm + gate + top-2 routing. One block per token. Writes fp16 normed acts.
__global__ __launch_bounds__(256) void route_kernel(const float* __restrict__ x,
                                                    const float* __restrict__ gw)
{
    const int t   = blockIdx.x;
    const int tid = threadIdx.x;
    __shared__ float s_x[D_MODEL];
    __shared__ float s_red[8];
    __shared__ float s_logit[N_EXP];
    __shared__ float s_rstd;

    const float* xr = x + (size_t)t * D_MODEL;
    float ss = 0.f;
    for (int i = tid; i < D_MODEL; i += 256) {
        float v = xr[i]; s_x[i] = v; ss += v * v;
    }
#pragma unroll
    for (int o = 16; o > 0; o >>= 1) ss += __shfl_xor_sync(0xffffffffu, ss, o);
    if ((tid & 31) == 0) s_red[tid >> 5] = ss;
    __syncthreads();
    if (tid == 0) {
        float tot = 0.f;
#pragma unroll
        for (int i = 0; i < 8; i++) tot += s_red[i];
        s_rstd = rsqrtf(tot * (1.0f / D_MODEL) + 1e-6f);
    }
    __syncthreads();
    const float rstd = s_rstd;
    for (int i = tid; i < D_MODEL; i += 256) {
        float v = s_x[i] * rstd;
        s_x[i] = v;
        g_xnh[(size_t)t * D_MODEL + i] = __float2half_rn(v);
    }
    __syncthreads();

    const int w = tid >> 5, lane = tid & 31;
    const float* ge = gw + (size_t)w * D_MODEL;
    float acc = 0.f;
    for (int i = lane; i < D_MODEL; i += 32) acc += s_x[i] * ge[i];
#pragma unroll
    for (int o = 16; o > 0; o >>= 1) acc += __shfl_xor_sync(0xffffffffu, acc, o);
    if (lane == 0) s_logit[w] = acc;
    __syncthreads();

    if (tid == 0) {
        float l[8];
#pragma unroll
        for (int i = 0; i < 8; i++) l[i] = s_logit[i];
        int i0 = 0;
        for (int i = 1; i < 8; i++) if (l[i] > l[i0]) i0 = i;
        int i1 = (i0 == 0) ? 1 : 0;
        for (int i = 0; i < 8; i++) if (i != i0 && l[i] > l[i1]) i1 = i;
        float e1 = expf(l[i1] - l[i0]);
        float w0 = 1.0f / (1.0f + e1);
        float w1v = 1.0f - w0;

        int s0 = atomicAdd(&g_cnt[i0], 1);
        g_idx[i0 * SEG + s0] = t;
        g_wt[i0 * SEG + s0]  = w0;
        g_tokseg[2 * t]      = i0 * SEG + s0;

        int s1 = atomicAdd(&g_cnt[i1], 1);
        g_idx[i1 * SEG + s1] = t;
        g_wt[i1 * SEG + s1]  = w1v;
        g_tokseg[2 * t + 1]  = i1 * SEG + s1;
    }
}

// ---------------------------------------------------------------------------
// Up GEMM (fp16 m16n8k16): CTA 128(M) x 256(B-rows = 128 w-cols interleaved w1/w3).
// 8 warps 2(M)x4(N), warp tile 64x64. 4-stage cp.async pipeline, K-chunk 32.
__global__ __launch_bounds__(256)
void up_mma()
{
    const int e   = blockIdx.z;
    const int cnt = (e == N_EXP) ? T_TOKENS : g_cnt[e];
    const int m0  = blockIdx.y * 128;
    if (m0 >= cnt) return;
    const int bx  = blockIdx.x;             // 128 w-cols => 256 interleaved B rows

    extern __shared__ __half sm[];
    __shared__ int s_row[128];

    const int tid  = threadIdx.x;
    const int wid  = tid >> 5;
    const int lane = tid & 31;
    const int g    = lane >> 2;
    const int p    = lane & 3;
    const int wm   = wid & 1;     // 0..1  (64 M each)
    const int wn   = wid >> 1;    // 0..3  (64 B-rows each)

    if (tid < 128) {
        int m = m0 + tid;
        s_row[tid] = (m < cnt) ? ((e == N_EXP) ? m : g_idx[e * SEG + m]) : 0;
    }
    __syncthreads();

    const __half* Bsrc = g_w13r + ((size_t)e * 2 * D_FF + (size_t)bx * 256) * D_MODEL;

    auto load_stage = [&](int k0, int s) {
        __half* As = sm + s * STAGE_H;
        __half* Bs = As + 128 * STRIDE;
        // A: 128 rows x 64B (4 x 16B chunks) gathered
#pragma unroll
        for (int it = 0; it < 2; it++) {
            int id = it * 256 + tid;
            int r = id >> 2, c = id & 3;
            const __half* src = g_xnh + (size_t)s_row[r] * D_MODEL + k0 + c * 8;
            CP_ASYNC16(smem_u32(As + r * STRIDE + c * 8), src);
        }
        // B: 256 rows x 64B
#pragma unroll
        for (int it = 0; it < 4; it++) {
            int id = it * 256 + tid;
            int r = id >> 2, c = id & 3;
            const __half* src = Bsrc + (size_t)r * D_MODEL + k0 + c * 8;
            CP_ASYNC16(smem_u32(Bs + r * STRIDE + c * 8), src);
        }
        CP_COMMIT();
    };

    float acc[4][8][4] = {};

    auto compute = [&](int s) {
        const __half* As = sm + s * STAGE_H + (wm * 64) * STRIDE;
        const __half* Bs = sm + s * STAGE_H + 128 * STRIDE + (wn * 64) * STRIDE;
#pragma unroll
        for (int kk = 0; kk < 32; kk += 16) {
            uint32_t a[4][4];
#pragma unroll
            for (int mi = 0; mi < 4; mi++) {
                const uint32_t* lo = (const uint32_t*)(As + (mi * 16 + g) * STRIDE + kk);
                const uint32_t* hi = (const uint32_t*)(As + (mi * 16 + g + 8) * STRIDE + kk);
                a[mi][0] = lo[p];
                a[mi][1] = hi[p];
                a[mi][2] = lo[p + 4];
                a[mi][3] = hi[p + 4];
            }
#pragma unroll
            for (int ni = 0; ni < 8; ni++) {
                const uint32_t* q = (const uint32_t*)(Bs + (ni * 8 + g) * STRIDE + kk);
                uint32_t b0 = q[p], b1 = q[p + 4];
#pragma unroll
                for (int mi = 0; mi < 4; mi++)
                    mma16(acc[mi][ni], a[mi][mi ? 1 - 1 : 0] == 0 && false ? a[mi] : a[mi], b0, b1);
            }
        }
    };

    const int NK = D_MODEL / 32;   // 32
    load_stage(0, 0);
    load_stage(32, 1);
    load_stage(64, 2);
    for (int k = 0; k < NK; k++) {
        CP_WAIT2();
        __syncthreads();
        compute(k & 3);
        if (k + 3 < NK) load_stage((k + 3) * 32, (k + 3) & 3);
        else            CP_COMMIT();   // keep group counting consistent
    }

    // Epilogue: col j = bx*128 + wn*32 + ni*4 + p; u=c[0|2] (w1), v=c[1|3] (w3)
#pragma unroll
    for (int mi = 0; mi < 4; mi++) {
#pragma unroll
        for (int hh = 0; hh < 2; hh++) {
            int m = m0 + wm * 64 + mi * 16 + g + hh * 8;
            if (m >= cnt) continue;
            __half* Hp = g_H + ((size_t)e * SEG + m) * D_FF + bx * 128 + wn * 32;
#pragma unroll
            for (int ni = 0; ni < 8; ni++) {
                float u = acc[mi][ni][hh * 2 + 0];
                float v = acc[mi][ni][hh * 2 + 1];
                Hp[ni * 4 + p] = __float2half_rn(u * normcdff(u) * v);
            }
        }
    }
}

// ---------------------------------------------------------------------------
// Down GEMM (fp16 m16n8k16): CTA 256(M) x 128(N). 8 warps 4(M)x2(N), warp 64x64.
__global__ __launch_bounds__(256)
void down_mma()
{
    const int e   = blockIdx.z;
    const int cnt = (e == N_EXP) ? T_TOKENS : g_cnt[e];
    const int m0  = blockIdx.y * 256;
    if (m0 >= cnt) return;
    const int bx  = blockIdx.x;             // 128 output cols

    extern __shared__ __half sm[];

    const int tid  = threadIdx.x;
    const int wid  = tid >> 5;
    const int lane = tid & 31;
    const int g    = lane >> 2;
    const int p    = lane & 3;
    const int wm   = wid >> 1;    // 0..3
    const int wn   = wid & 1;     // 0..1

    const __half* Asrc = g_H + ((size_t)e * SEG + m0) * D_FF;
    const __half* Bsrc = g_w2r + ((size_t)e * D_MODEL + (size_t)bx * 128) * D_FF;

    auto load_stage = [&](int k0, int s) {
        __half* As = sm + s * STAGE_H;
        __half* Bs = As + 256 * STRIDE;
#pragma unroll
        for (int it = 0; it < 4; it++) {
            int id = it * 256 + tid;
            int r = id >> 2, c = id & 3;
            const __half* src = Asrc + (size_t)r * D_FF + k0 + c * 8;
            CP_ASYNC16(smem_u32(As + r * STRIDE + c * 8), src);
        }
#pragma unroll
        for (int it = 0; it < 2; it++) {
            int id = it * 256 + tid;
            int r = id >> 2, c = id & 3;
            const __half* src = Bsrc + (size_t)r * D_FF + k0 + c * 8;
            CP_ASYNC16(smem_u32(Bs + r * STRIDE + c * 8), src);
        }
        CP_COMMIT();
    };

    float acc[4][8][4] = {};

    auto compute = [&](int s) {
        const __half* As = sm + s * STAGE_H + (wm * 64) * STRIDE;
        const __half* Bs = sm + s * STAGE_H + 256 * STRIDE + (wn * 64) * STRIDE;
#pragma unroll
        for (int kk = 0; kk < 32; kk += 16) {
            uint32_t a[4][4];
#pragma unroll
            for (int mi = 0; mi < 4; mi++) {
                const uint32_t* lo = (const uint32_t*)(As + (mi * 16 + g) * STRIDE + kk);
                const uint32_t* hi = (const uint32_t*)(As + (mi * 16 + g + 8) * STRIDE + kk);
                a[mi][0] = lo[p];
                a[mi][1] = hi[p];
                a[mi][2] = lo[p + 4];
                a[mi][3] = hi[p + 4];
            }
#pragma unroll
            for (int ni = 0; ni < 8; ni++) {
                const uint32_t* q = (const uint32_t*)(Bs + (ni * 8 + g) * STRIDE + kk);
                uint32_t b0 = q[p], b1 = q[p + 4];
#pragma unroll
                for (int mi = 0; mi < 4; mi++)
                    mma16(acc[mi][ni], a[mi], b0, b1);
            }
        }
    };

    const int NK = D_FF / 32;   // 88
    load_stage(0, 0);
    load_stage(32, 1);
    load_stage(64, 2);
    for (int k = 0; k < NK; k++) {
        CP_WAIT2();
        __syncthreads();
        compute(k & 3);
        if (k + 3 < NK) load_stage((k + 3) * 32, (k + 3) & 3);
        else            CP_COMMIT();
    }

    // Epilogue: scale by combine weight -> g_Y (fp32), float2 stores
#pragma unroll
    for (int mi = 0; mi < 4; mi++) {
#pragma unroll
        for (int hh = 0; hh < 2; hh++) {
            int m = m0 + wm * 64 + mi * 16 + g + hh * 8;
            if (m >= cnt) continue;
            float wt = (e == N_EXP) ? 1.0f : g_wt[e * SEG + m];
            float* Yp = g_Y + ((size_t)e * SEG + m) * D_MODEL + bx * 128 + wn * 64;
#pragma unroll
            for (int ni = 0; ni < 8; ni++) {
                float2 o = {acc[mi][ni][hh * 2 + 0] * wt,
                            acc[mi][ni][hh * 2 + 1] * wt};
                *(float2*)(Yp + ni * 8 + 2 * p) = o;
            }
        }
    }
}

// ---------------------------------------------------------------------------
__global__ void combine_kernel(const float* __restrict__ x, float* __restrict__ out)
{
    const int t = blockIdx.x;
    const int s0 = g_tokseg[2 * t], s1 = g_tokseg[2 * t + 1];
    const float* xr  = x + (size_t)t * D_MODEL;
    const float* ysh = g_Y + ((size_t)N_EXP * SEG + t) * D_MODEL;
    const float* y0  = g_Y + (size_t)s0 * D_MODEL;
    const float* y1  = g_Y + (size_t)s1 * D_MODEL;
    float* o = out + (size_t)t * D_MODEL;
    for (int i = threadIdx.x; i < D_MODEL; i += blockDim.x)
        o[i] = xr[i] + ysh[i] + y0[i] + y1[i];
}

// ---------------------------------------------------------------------------
extern "C" void kernel_launch(void* const* d_in, const int* in_sizes, int n_in,
                              void* d_out, int out_size)
{
    const float* x   = (const float*)d_in[0];
    const float* gw  = (const float*)d_in[1];
    const float* w1  = (const float*)d_in[2];
    const float* w2  = (const float*)d_in[3];
    const float* w3  = (const float*)d_in[4];
    const float* sw1 = (const float*)d_in[5];
    const float* sw2 = (const float*)d_in[6];
    const float* sw3 = (const float*)d_in[7];
    float* out = (float*)d_out;

    cudaFuncSetAttribute(up_mma,   cudaFuncAttributeMaxDynamicSharedMemorySize, SMEM_DYN);
    cudaFuncSetAttribute(down_mma, cudaFuncAttributeMaxDynamicSharedMemorySize, SMEM_DYN);

    zero_cnt_kernel<<<1, 32>>>();
    conv_w13<<<NSEG * 2 * D_FF, 256>>>(w1, w3, sw1, sw3);
    conv_w2<<<NSEG * D_MODEL, 256>>>(w2, sw2);
    route_kernel<<<T_TOKENS, 256>>>(x, gw);
    up_mma<<<dim3(D_FF / 128, T_TOKENS / 128, NSEG), 256, SMEM_DYN>>>();
    down_mma<<<dim3(D_MODEL / 128, T_TOKENS / 256, NSEG), 256, SMEM_DYN>>>();
    combine_kernel<<<T_TOKENS, 256>>>(x, out);
}

// round 13
// speedup vs baseline: 5.0751x; 1.0324x over previous
#include <cuda_runtime.h>
#include <cuda_fp16.h>
#include <math.h>
#include <stdint.h>

#define D_MODEL 1024
#define D_FF    2816
#define N_EXP   8
#define NSEG    9            // 8 routed experts + 1 shared (index 8)
#define T_TOKENS 4096
#define SEG     4096

// ---------------- scratch (device globals; no allocations) ----------------
__device__ __half g_xnh[(size_t)T_TOKENS * D_MODEL];            // fp16 normed acts
__device__ __half g_w13r[(size_t)NSEG * 2 * D_FF * D_MODEL];    // interleaved w1/w3 fp16
__device__ __half g_w2r[(size_t)NSEG * D_MODEL * D_FF];         // w2 fp16
__device__ __half g_H[(size_t)NSEG * SEG * D_FF];               // hidden acts fp16
__device__ float  g_Y[(size_t)NSEG * SEG * D_MODEL];            // expert outputs fp32
__device__ int    g_idx[NSEG * SEG];
__device__ float  g_wt[N_EXP * SEG];
__device__ int    g_cnt[16];
__device__ int    g_tokseg[T_TOKENS * 2];

// ---------------- helpers ----------------
__device__ __forceinline__ uint32_t smem_u32(const void* p) {
    uint32_t a;
    asm("{ .reg .u64 t; cvta.to.shared.u64 t, %1; cvt.u32.u64 %0, t; }" : "=r"(a) : "l"(p));
    return a;
}
__device__ __forceinline__ void mma16(float c[4], const uint32_t a[4],
                                      uint32_t b0, uint32_t b1) {
    asm volatile(
        "mma.sync.aligned.m16n8k16.row.col.f32.f16.f16.f32 "
        "{%0,%1,%2,%3}, {%4,%5,%6,%7}, {%8,%9}, {%0,%1,%2,%3};"
        : "+f"(c[0]), "+f"(c[1]), "+f"(c[2]), "+f"(c[3])
        : "r"(a[0]), "r"(a[1]), "r"(a[2]), "r"(a[3]), "r"(b0), "r"(b1));
}
__device__ __forceinline__ void ldsm4(uint32_t r[4], uint32_t addr) {
    asm volatile("ldmatrix.sync.aligned.m8n8.x4.shared.b16 {%0,%1,%2,%3}, [%4];"
                 : "=r"(r[0]), "=r"(r[1]), "=r"(r[2]), "=r"(r[3]) : "r"(addr));
}
#define CP_ASYNC16(d, s) asm volatile("cp.async.cg.shared.global [%0], [%1], 16;" :: "r"(d), "l"(s) : "memory")
#define CP_COMMIT()      asm volatile("cp.async.commit_group;" ::: "memory")
#define CP_WAIT2()       asm volatile("cp.async.wait_group 2;" ::: "memory")

// stage: A-rows + B-rows, stride 40 halves (80B): conflict-free for cp.async
// stores AND ldmatrix 8-row phases (banks rotate by 20 per row -> all distinct).
#define STRIDE     40
#define STAGE_H    ((128 + 256) * STRIDE)     // 15360 halves = 30720 B
#define STAGE_B    (STAGE_H * 2)
#define N_STAGES   4
#define SMEM_DYN   (N_STAGES * STAGE_B)       // 122880 B

// ---------------------------------------------------------------------------
__global__ void zero_cnt_kernel() {
    if (threadIdx.x < 16) g_cnt[threadIdx.x] = 0;
}

// weights -> fp16, grid-stride. w1/w3 interleaved by output column:
// g_w13r row 2j = w1[j], 2j+1 = w3[j] (per expert; shared at e=8).
__global__ __launch_bounds__(256) void conv_w13(
    const float* __restrict__ w1, const float* __restrict__ w3,
    const float* __restrict__ sw1, const float* __restrict__ sw3)
{
    const int64_t total = (int64_t)NSEG * 2 * D_FF * (D_MODEL / 4);
    for (int64_t idx = (int64_t)blockIdx.x * 256 + threadIdx.x;
         idx < total; idx += (int64_t)gridDim.x * 256) {
        int64_t r = idx >> 8;            // row (D_MODEL/4 = 256 chunks per row)
        int     c = (int)(idx & 255);
        int e  = (int)(r / (2 * D_FF));
        int rr = (int)(r % (2 * D_FF));
        int j = rr >> 1, h = rr & 1;
        const float* src;
        if (e < N_EXP) src = (h ? w3 : w1) + ((size_t)e * D_FF + j) * D_MODEL;
        else           src = (h ? sw3 : sw1) + (size_t)j * D_MODEL;
        float4 v = ((const float4*)src)[c];
        __half* dst = g_w13r + r * D_MODEL + c * 4;
        *(__half2*)(dst)     = __floats2half2_rn(v.x, v.y);
        *(__half2*)(dst + 2) = __floats2half2_rn(v.z, v.w);
    }
}

__global__ __launch_bounds__(256) void conv_w2(
    const float* __restrict__ w2, const float* __restrict__ sw2)
{
    const int64_t total = (int64_t)NSEG * D_MODEL * (D_FF / 4);
    for (int64_t idx = (int64_t)blockIdx.x * 256 + threadIdx.x;
         idx < total; idx += (int64_t)gridDim.x * 256) {
        int64_t r = idx / (D_FF / 4);
        int     c = (int)(idx % (D_FF / 4));
        int e = (int)(r / D_MODEL), rr = (int)(r % D_MODEL);
        const float* src = (e < N_EXP) ? (w2 + ((size_t)e * D_MODEL + rr) * D_FF)
                                       : (sw2 + (size_t)rr * D_FF);
        float4 v = ((const float4*)src)[c];
        __half* dst = g_w2r + r * D_FF + c * 4;
        *(__half2*)(dst)     = __floats2half2_rn(v.x, v.y);
        *(__half2*)(dst + 2) = __floats2half2_rn(v.z, v.w);
    }
}

// RMSNorm + gate + top-2 routing. One block per token. Writes fp16 normed acts.
__global__ __launch_bounds__(256) void route_kernel(const float* __restrict__ x,
                                                    const float* __restrict__ gw)
{
    const int t   = blockIdx.x;
    const int tid = threadIdx.x;
    __shared__ float s_x[D_MODEL];
    __shared__ float s_red[8];
    __shared__ float s_logit[N_EXP];
    __shared__ float s_rstd;

    const float* xr = x + (size_t)t * D_MODEL;
    float ss = 0.f;
    for (int i = tid; i < D_MODEL; i += 256) {
        float v = xr[i]; s_x[i] = v; ss += v * v;
    }
#pragma unroll
    for (int o = 16; o > 0; o >>= 1) ss += __shfl_xor_sync(0xffffffffu, ss, o);
    if ((tid & 31) == 0) s_red[tid >> 5] = ss;
    __syncthreads();
    if (tid == 0) {
        float tot = 0.f;
#pragma unroll
        for (int i = 0; i < 8; i++) tot += s_red[i];
        s_rstd = rsqrtf(tot * (1.0f / D_MODEL) + 1e-6f);
    }
    __syncthreads();
    const float rstd = s_rstd;
    for (int i = tid; i < D_MODEL; i += 256) {
        float v = s_x[i] * rstd;
        s_x[i] = v;
        g_xnh[(size_t)t * D_MODEL + i] = __float2half_rn(v);
    }
    __syncthreads();

    const int w = tid >> 5, lane = tid & 31;
    const float* ge = gw + (size_t)w * D_MODEL;
    float acc = 0.f;
    for (int i = lane; i < D_MODEL; i += 32) acc += s_x[i] * ge[i];
#pragma unroll
    for (int o = 16; o > 0; o >>= 1) acc += __shfl_xor_sync(0xffffffffu, acc, o);
    if (lane == 0) s_logit[w] = acc;
    __syncthreads();

    if (tid == 0) {
        float l[8];
#pragma unroll
        for (int i = 0; i < 8; i++) l[i] = s_logit[i];
        int i0 = 0;
        for (int i = 1; i < 8; i++) if (l[i] > l[i0]) i0 = i;
        int i1 = (i0 == 0) ? 1 : 0;
        for (int i = 0; i < 8; i++) if (i != i0 && l[i] > l[i1]) i1 = i;
        float e1 = expf(l[i1] - l[i0]);
        float w0 = 1.0f / (1.0f + e1);
        float w1v = 1.0f - w0;

        int s0 = atomicAdd(&g_cnt[i0], 1);
        g_idx[i0 * SEG + s0] = t;
        g_wt[i0 * SEG + s0]  = w0;
        g_tokseg[2 * t]      = i0 * SEG + s0;

        int s1 = atomicAdd(&g_cnt[i1], 1);
        g_idx[i1 * SEG + s1] = t;
        g_wt[i1 * SEG + s1]  = w1v;
        g_tokseg[2 * t + 1]  = i1 * SEG + s1;
    }
}

// ---------------------------------------------------------------------------
// Up GEMM (fp16 m16n8k16 + ldmatrix): CTA 128(M) x 256(B-rows, interleaved w1/w3).
// 8 warps 2(M)x4(N), warp tile 64x64. 4-stage cp.async pipeline, K-chunk 32.
__global__ __launch_bounds__(256)
void up_mma()
{
    const int e   = blockIdx.z;
    const int cnt = (e == N_EXP) ? T_TOKENS : g_cnt[e];
    const int m0  = blockIdx.y * 128;
    if (m0 >= cnt) return;
    const int bx  = blockIdx.x;             // 128 w-cols => 256 interleaved B rows

    extern __shared__ __half sm[];
    const uint32_t sbase = smem_u32(sm);
    __shared__ int s_row[128];

    const int tid  = threadIdx.x;
    const int wid  = tid >> 5;
    const int lane = tid & 31;
    const int g    = lane >> 2;
    const int p    = lane & 3;
    const int wm   = wid & 1;     // 0..1  (64 M each)
    const int wn   = wid >> 1;    // 0..3  (64 B-rows each)

    if (tid < 128) {
        int m = m0 + tid;
        s_row[tid] = (m < cnt) ? ((e == N_EXP) ? m : g_idx[e * SEG + m]) : 0;
    }
    __syncthreads();

    const __half* Bsrc = g_w13r + ((size_t)e * 2 * D_FF + (size_t)bx * 256) * D_MODEL;

    // lane-dependent ldmatrix offsets (bytes, within a stage)
    const uint32_t a_loff =
        ((uint32_t)(wm * 64 + (lane & 7) + ((lane >> 3) & 1) * 8) * STRIDE +
         ((lane >> 4) & 1) * 8) * 2;
    const uint32_t b_loff = (uint32_t)128 * STRIDE * 2 +
        ((uint32_t)(wn * 64 + (lane >> 4) * 8 + (lane & 7)) * STRIDE +
         ((lane >> 3) & 1) * 8) * 2;

    auto load_stage = [&](int k0, int s) {
        __half* As = sm + s * STAGE_H;
        __half* Bs = As + 128 * STRIDE;
#pragma unroll
        for (int it = 0; it < 2; it++) {
            int id = it * 256 + tid;
            int r = id >> 2, c = id & 3;
            const __half* src = g_xnh + (size_t)s_row[r] * D_MODEL + k0 + c * 8;
            CP_ASYNC16(smem_u32(As + r * STRIDE + c * 8), src);
        }
#pragma unroll
        for (int it = 0; it < 4; it++) {
            int id = it * 256 + tid;
            int r = id >> 2, c = id & 3;
            const __half* src = Bsrc + (size_t)r * D_MODEL + k0 + c * 8;
            CP_ASYNC16(smem_u32(Bs + r * STRIDE + c * 8), src);
        }
        CP_COMMIT();
    };

    float acc[4][8][4] = {};

    auto compute = [&](int s) {
        const uint32_t Aa = sbase + s * STAGE_B + a_loff;
        const uint32_t Ba = sbase + s * STAGE_B + b_loff;
#pragma unroll
        for (int kk = 0; kk < 2; kk++) {       // kk*16 within chunk (32B smem step)
            uint32_t a[4][4];
#pragma unroll
            for (int mi = 0; mi < 4; mi++)
                ldsm4(a[mi], Aa + mi * (16 * STRIDE * 2) + kk * 32);
#pragma unroll
            for (int nip = 0; nip < 4; nip++) {
                uint32_t b[4];                 // {b0(ni), b1(ni), b0(ni+1), b1(ni+1)}
                ldsm4(b, Ba + nip * (16 * STRIDE * 2) + kk * 32);
#pragma unroll
                for (int mi = 0; mi < 4; mi++) {
                    mma16(acc[mi][2 * nip + 0], a[mi], b[0], b[1]);
                    mma16(acc[mi][2 * nip + 1], a[mi], b[2], b[3]);
                }
            }
        }
    };

    const int NK = D_MODEL / 32;   // 32
    load_stage(0, 0);
    load_stage(32, 1);
    load_stage(64, 2);
    for (int k = 0; k < NK; k++) {
        CP_WAIT2();
        __syncthreads();
        compute(k & 3);
        if (k + 3 < NK) load_stage((k + 3) * 32, (k + 3) & 3);
        else            CP_COMMIT();   // keep group counting consistent
    }

    // Epilogue: col j = bx*128 + wn*32 + ni*4 + p; u=c[even] (w1), v=c[odd] (w3)
#pragma unroll
    for (int mi = 0; mi < 4; mi++) {
#pragma unroll
        for (int hh = 0; hh < 2; hh++) {
            int m = m0 + wm * 64 + mi * 16 + g + hh * 8;
            if (m >= cnt) continue;
            __half* Hp = g_H + ((size_t)e * SEG + m) * D_FF + bx * 128 + wn * 32;
#pragma unroll
            for (int ni = 0; ni < 8; ni++) {
                float u = acc[mi][ni][hh * 2 + 0];
                float v = acc[mi][ni][hh * 2 + 1];
                Hp[ni * 4 + p] = __float2half_rn(u * normcdff(u) * v);
            }
        }
    }
}

// ---------------------------------------------------------------------------
// Down GEMM (fp16 m16n8k16 + ldmatrix): CTA 256(M) x 128(N). 8 warps 4x2, warp 64x64.
__global__ __launch_bounds__(256)
void down_mma()
{
    const int e   = blockIdx.z;
    const int cnt = (e == N_EXP) ? T_TOKENS : g_cnt[e];
    const int m0  = blockIdx.y * 256;
    if (m0 >= cnt) return;
    const int bx  = blockIdx.x;             // 128 output cols

    extern __shared__ __half sm[];
    const uint32_t sbase = smem_u32(sm);

    const int tid  = threadIdx.x;
    const int wid  = tid >> 5;
    const int lane = tid & 31;
    const int g    = lane >> 2;
    const int p    = lane & 3;
    const int wm   = wid >> 1;    // 0..3
    const int wn   = wid & 1;     // 0..1

    const __half* Asrc = g_H + ((size_t)e * SEG + m0) * D_FF;
    const __half* Bsrc = g_w2r + ((size_t)e * D_MODEL + (size_t)bx * 128) * D_FF;

    const uint32_t a_loff =
        ((uint32_t)(wm * 64 + (lane & 7) + ((lane >> 3) & 1) * 8) * STRIDE +
         ((lane >> 4) & 1) * 8) * 2;
    const uint32_t b_loff = (uint32_t)256 * STRIDE * 2 +
        ((uint32_t)(wn * 64 + (lane >> 4) * 8 + (lane & 7)) * STRIDE +
         ((lane >> 3) & 1) * 8) * 2;

    auto load_stage = [&](int k0, int s) {
        __half* As = sm + s * STAGE_H;
        __half* Bs = As + 256 * STRIDE;
#pragma unroll
        for (int it = 0; it < 4; it++) {
            int id = it * 256 + tid;
            int r = id >> 2, c = id & 3;
            const __half* src = Asrc + (size_t)r * D_FF + k0 + c * 8;
            CP_ASYNC16(smem_u32(As + r * STRIDE + c * 8), src);
        }
#pragma unroll
        for (int it = 0; it < 2; it++) {
            int id = it * 256 + tid;
            int r = id >> 2, c = id & 3;
            const __half* src = Bsrc + (size_t)r * D_FF + k0 + c * 8;
            CP_ASYNC16(smem_u32(Bs + r * STRIDE + c * 8), src);
        }
        CP_COMMIT();
    };

    float acc[4][8][4] = {};

    auto compute = [&](int s) {
        const uint32_t Aa = sbase + s * STAGE_B + a_loff;
        const uint32_t Ba = sbase + s * STAGE_B + b_loff;
#pragma unroll
        for (int kk = 0; kk < 2; kk++) {
            uint32_t a[4][4];
#pragma unroll
            for (int mi = 0; mi < 4; mi++)
                ldsm4(a[mi], Aa + mi * (16 * STRIDE * 2) + kk * 32);
#pragma unroll
            for (int nip = 0; nip < 4; nip++) {
                uint32_t b[4];
                ldsm4(b, Ba + nip * (16 * STRIDE * 2) + kk * 32);
#pragma unroll
                for (int mi = 0; mi < 4; mi++) {
                    mma16(acc[mi][2 * nip + 0], a[mi], b[0], b[1]);
                    mma16(acc[mi][2 * nip + 1], a[mi], b[2], b[3]);
                }
            }
        }
    };

    const int NK = D_FF / 32;   // 88
    load_stage(0, 0);
    load_stage(32, 1);
    load_stage(64, 2);
    for (int k = 0; k < NK; k++) {
        CP_WAIT2();
        __syncthreads();
        compute(k & 3);
        if (k + 3 < NK) load_stage((k + 3) * 32, (k + 3) & 3);
        else            CP_COMMIT();
    }

    // Epilogue: scale by combine weight -> g_Y (fp32), float2 stores
#pragma unroll
    for (int mi = 0; mi < 4; mi++) {
#pragma unroll
        for (int hh = 0; hh < 2; hh++) {
            int m = m0 + wm * 64 + mi * 16 + g + hh * 8;
            if (m >= cnt) continue;
            float wt = (e == N_EXP) ? 1.0f : g_wt[e * SEG + m];
            float* Yp = g_Y + ((size_t)e * SEG + m) * D_MODEL + bx * 128 + wn * 64;
#pragma unroll
            for (int ni = 0; ni < 8; ni++) {
                float2 o = {acc[mi][ni][hh * 2 + 0] * wt,
                            acc[mi][ni][hh * 2 + 1] * wt};
                *(float2*)(Yp + ni * 8 + 2 * p) = o;
            }
        }
    }
}

// ---------------------------------------------------------------------------
__global__ void combine_kernel(const float* __restrict__ x, float* __restrict__ out)
{
    const int t = blockIdx.x;
    const int s0 = g_tokseg[2 * t], s1 = g_tokseg[2 * t + 1];
    const float* xr  = x + (size_t)t * D_MODEL;
    const float* ysh = g_Y + ((size_t)N_EXP * SEG + t) * D_MODEL;
    const float* y0  = g_Y + (size_t)s0 * D_MODEL;
    const float* y1  = g_Y + (size_t)s1 * D_MODEL;
    float* o = out + (size_t)t * D_MODEL;
    for (int i = threadIdx.x; i < D_MODEL; i += blockDim.x)
        o[i] = xr[i] + ysh[i] + y0[i] + y1[i];
}

// ---------------------------------------------------------------------------
extern "C" void kernel_launch(void* const* d_in, const int* in_sizes, int n_in,
                              void* d_out, int out_size)
{
    const float* x   = (const float*)d_in[0];
    const float* gw  = (const float*)d_in[1];
    const float* w1  = (const float*)d_in[2];
    const float* w2  = (const float*)d_in[3];
    const float* w3  = (const float*)d_in[4];
    const float* sw1 = (const float*)d_in[5];
    const float* sw2 = (const float*)d_in[6];
    const float* sw3 = (const float*)d_in[7];
    float* out = (float*)d_out;

    cudaFuncSetAttribute(up_mma,   cudaFuncAttributeMaxDynamicSharedMemorySize, SMEM_DYN);
    cudaFuncSetAttribute(down_mma, cudaFuncAttributeMaxDynamicSharedMemorySize, SMEM_DYN);

    zero_cnt_kernel<<<1, 32>>>();
    conv_w13<<<2048, 256>>>(w1, w3, sw1, sw3);
    conv_w2<<<1024, 256>>>(w2, sw2);
    route_kernel<<<T_TOKENS, 256>>>(x, gw);
    up_mma<<<dim3(D_FF / 128, T_TOKENS / 128, NSEG), 256, SMEM_DYN>>>();
    down_mma<<<dim3(D_MODEL / 128, T_TOKENS / 256, NSEG), 256, SMEM_DYN>>>();
    combine_kernel<<<T_TOKENS, 256>>>(x, out);
}